// round 10
// baseline (speedup 1.0000x reference)
#include <cuda_runtime.h>
#include <cuda_bf16.h>
#include <cstdint>

// Problem constants
#define DIM 256
#define NATOMS 512
#define NCOLS 65536

// ---------------- device scratch (no allocation allowed) ----------------
__device__ float g_G[DIM * DIM];        // Gram matrix G = D D^T  (256x256)
__device__ float g_Ainv[128 * 128];
__device__ float g_T[128 * 128];        // T = Ainv * B
__device__ float g_S[128 * 128];        // Schur complement
__device__ float g_Sinv[128 * 128];
__device__ float g_M12[128 * 128];
__device__ float g_Minv[DIM * DIM];     // G^{-1} (256x256)
__device__ float g_Dt[DIM * NATOMS];    // D (= dictionary^T), [256][512]
__device__ int   g_bar[8];              // software grid-barrier counters

// bf16 split operands (16-byte aligned for cp.async 16B)
__device__ __align__(16) __nv_bfloat16 g_Xt_hi[(size_t)NCOLS * DIM];  // [m][k]
__device__ __align__(16) __nv_bfloat16 g_Xt_lo[(size_t)NCOLS * DIM];
__device__ __align__(16) __nv_bfloat16 g_Wt_hi[NATOMS * DIM];         // [n][k]
__device__ __align__(16) __nv_bfloat16 g_Wt_lo[NATOMS * DIM];

// ================= helpers (family-portable PTX only) =================
__device__ __forceinline__ uint32_t smem_u32(const void* p) {
    uint32_t a;
    asm("{ .reg .u64 t; cvta.to.shared.u64 t, %1; cvt.u32.u64 %0, t; }" : "=r"(a) : "l"(p));
    return a;
}
__device__ __forceinline__ uint32_t lds32(uint32_t addr) {
    uint32_t v;
    asm volatile("ld.shared.b32 %0, [%1];" : "=r"(v) : "r"(addr));
    return v;
}
__device__ __forceinline__ void cp_async16(uint32_t smem_addr, const void* gptr) {
    asm volatile("cp.async.cg.shared.global [%0], [%1], 16;" :: "r"(smem_addr), "l"(gptr));
}
__device__ __forceinline__ void cp_commit() {
    asm volatile("cp.async.commit_group;" ::: "memory");
}
__device__ __forceinline__ void cp_wait1() {
    asm volatile("cp.async.wait_group 1;" ::: "memory");
}
__device__ __forceinline__ void cp_wait0() {
    asm volatile("cp.async.wait_group 0;" ::: "memory");
}
__device__ __forceinline__ void mma16816(float* d, uint32_t a0, uint32_t a1, uint32_t a2,
                                         uint32_t a3, uint32_t b0, uint32_t b1) {
    asm volatile(
        "mma.sync.aligned.m16n8k16.row.col.f32.bf16.bf16.f32 "
        "{%0,%1,%2,%3}, {%4,%5,%6,%7}, {%8,%9}, {%0,%1,%2,%3};"
        : "+f"(d[0]), "+f"(d[1]), "+f"(d[2]), "+f"(d[3])
        : "r"(a0), "r"(a1), "r"(a2), "r"(a3), "r"(b0), "r"(b1));
}

// ---------------- prep: transpose dictionary -> g_Dt + reset barriers ----------
__global__ void prep_kernel(const float* __restrict__ dict) {
    if (blockIdx.x == 0 && threadIdx.x == 0 && threadIdx.y == 0) {
#pragma unroll
        for (int s = 0; s < 8; ++s) g_bar[s] = 0;
    }
    __shared__ float t[32][33];
    int bx = blockIdx.x & 7;     // 8 tiles along i (DIM)
    int by = blockIdx.x >> 3;    // 16 tiles along k (NATOMS)
    int x = bx * 32 + threadIdx.x;
#pragma unroll
    for (int r = 0; r < 32; r += 8) {
        int k = by * 32 + threadIdx.y + r;
        t[threadIdx.y + r][threadIdx.x] = dict[k * DIM + x];
    }
    __syncthreads();
#pragma unroll
    for (int r = 0; r < 32; r += 8) {
        int i = bx * 32 + threadIdx.y + r;
        g_Dt[i * NATOMS + by * 32 + threadIdx.x] = t[threadIdx.x][threadIdx.y + r];
    }
}

// ---------------- X [k][m] fp32 -> Xt_hi/lo [m][k] bf16 split ------------------
__global__ void xt_convert_kernel(const float* __restrict__ X) {
    __shared__ float t[32][33];
    int m0 = blockIdx.x * 32;
    int k0 = blockIdx.y * 32;
#pragma unroll
    for (int r = 0; r < 32; r += 8) {
        t[threadIdx.y + r][threadIdx.x] =
            X[(size_t)(k0 + threadIdx.y + r) * NCOLS + m0 + threadIdx.x];
    }
    __syncthreads();
#pragma unroll
    for (int r = 0; r < 32; r += 8) {
        int m = m0 + threadIdx.y + r;
        float v = t[threadIdx.x][threadIdx.y + r];
        __nv_bfloat16 h = __float2bfloat16(v);
        __nv_bfloat16 l = __float2bfloat16(v - __bfloat162float(h));
        size_t off = (size_t)m * DIM + k0 + threadIdx.x;
        g_Xt_hi[off] = h;
        g_Xt_lo[off] = l;
    }
}

// ---------------- persistent chain kernel --------------------------------------
// 128 CTAs x 1024 threads, all resident (128 <= 148 SMs). Software grid barriers.
#define NBLK 128

__device__ __forceinline__ void grid_bar(int s) {
    __syncthreads();
    if (threadIdx.x == 0) {
        __threadfence();
        atomicAdd(&g_bar[s], 1);
        while (atomicAdd(&g_bar[s], 0) < NBLK) __nanosleep(64);
        __threadfence();
    }
    __syncthreads();
}

// 1024-thread register-resident Gauss-Jordan 128x128 inverse (verified R3 code).
__device__ void gj128(int which) {
    const float* src = (which == 0) ? g_G : g_S;
    float* dst       = (which == 0) ? g_Ainv : g_Sinv;
    int lds          = (which == 0) ? DIM : 128;

    __shared__ float sh_col[128];
    __shared__ float sh_row[128];
    int tid = threadIdx.x;
    int row = tid >> 3;
    int seg = (tid & 7) << 4;
    float a[16];
#pragma unroll
    for (int c = 0; c < 16; ++c) a[c] = src[row * lds + seg + c];

    for (int k = 0; k < 128; ++k) {
#pragma unroll
        for (int c = 0; c < 16; ++c)
            if (seg + c == k) sh_col[row] = a[c];
        __syncthreads();
        float p = 1.0f / sh_col[k];
        float f = sh_col[row];
        if (row == k) {
#pragma unroll
            for (int c = 0; c < 16; ++c) {
                int j = seg + c;
                float v = (j == k) ? p : a[c] * p;
                a[c] = v;
                sh_row[j] = v;
            }
        }
        __syncthreads();
        if (row != k) {
#pragma unroll
            for (int c = 0; c < 16; ++c) {
                int j = seg + c;
                a[c] = (j == k) ? (-f * p) : (a[c] - f * sh_row[j]);
            }
        }
        __syncthreads();
    }
#pragma unroll
    for (int c = 0; c < 16; ++c) dst[row * 128 + seg + c] = a[c];
}

__global__ __launch_bounds__(1024, 1) void persist_kernel(const float* __restrict__ dict) {
    const int tid = threadIdx.x;
    const int c = blockIdx.x;           // 0..127
    __shared__ float srow[128];
    __shared__ float part[8][128];      // split-k partials
    __shared__ float sdcol[4][256];

    const int j8 = tid & 127;           // output column for split-k stages
    const int sl = tid >> 7;            // k-slice 0..7

    // ---- S0: gram. CTA c computes G rows {2c, 2c+1}; 1024 threads:
    // (j = tid&255, slice = tid>>8 covers 128 atoms each)
    {
        int j = tid & 255;
        int qs = tid >> 8;              // 0..3
        const float* dj = dict + j;
        const float* d0 = dict + 2 * c;
        const float* d1 = dict + 2 * c + 1;
        float s0 = 0.0f, s1 = 0.0f;
#pragma unroll 8
        for (int a = qs * 128; a < qs * 128 + 128; ++a) {
            float v = dj[a * DIM];
            s0 += d0[a * DIM] * v;
            s1 += d1[a * DIM] * v;
        }
        // reuse part[][] as [2][4][256] partial store
        ((float*)part)[qs * 256 + j] = s0;
        __syncthreads();
        float t0 = 0.0f;
        if (tid < 256) {
#pragma unroll
            for (int q = 0; q < 4; ++q) t0 += ((float*)part)[q * 256 + tid];
        }
        __syncthreads();
        ((float*)part)[qs * 256 + j] = s1;
        __syncthreads();
        if (tid < 256) {
            float t1 = 0.0f;
#pragma unroll
            for (int q = 0; q < 4; ++q) t1 += ((float*)part)[q * 256 + tid];
            g_G[(2 * c) * DIM + tid] = t0;
            g_G[(2 * c + 1) * DIM + tid] = t1;
        }
    }
    grid_bar(0);

    // ---- S1: invert A11 (CTA 0 only)
    if (c == 0) gj128(0);
    grid_bar(1);

    // ---- S2: T[c][j] = sum_k Ainv[c][k] * G[k][128+j]  (1024-thread split-k)
    if (tid < 128) srow[tid] = g_Ainv[c * 128 + tid];
    __syncthreads();
    {
        const float* gp = &g_G[(sl * 16) * DIM + 128 + j8];
        float s = 0.0f;
#pragma unroll
        for (int k = 0; k < 16; ++k) s += srow[sl * 16 + k] * gp[k * DIM];
        part[sl][j8] = s;
    }
    __syncthreads();
    if (tid < 128) {
        float s = 0.0f;
#pragma unroll
        for (int q = 0; q < 8; ++q) s += part[q][tid];
        g_T[c * 128 + tid] = s;
    }
    grid_bar(2);

    // ---- S3: S[c][j] = G[128+c][128+j] - sum_k G[k][128+c] * T[k][j]
    __syncthreads();
    if (tid < 128) srow[tid] = g_G[tid * DIM + 128 + c];
    __syncthreads();
    {
        const float* tp = &g_T[(sl * 16) * 128 + j8];
        float s = 0.0f;
#pragma unroll
        for (int k = 0; k < 16; ++k) s += srow[sl * 16 + k] * tp[k * 128];
        part[sl][j8] = s;
    }
    __syncthreads();
    if (tid < 128) {
        float s = g_G[(128 + c) * DIM + 128 + tid];
#pragma unroll
        for (int q = 0; q < 8; ++q) s -= part[q][tid];
        g_S[c * 128 + tid] = s;
    }
    grid_bar(3);

    // ---- S4: invert S (CTA 0 only)
    if (c == 0) gj128(1);
    grid_bar(4);

    // ---- S5: U = T*Sinv; M12 = -U; write M12/M21/Sinv quadrants of Minv
    __syncthreads();
    if (tid < 128) srow[tid] = g_T[c * 128 + tid];
    __syncthreads();
    {
        const float* sp = &g_Sinv[(sl * 16) * 128 + j8];
        float s = 0.0f;
#pragma unroll
        for (int k = 0; k < 16; ++k) s += srow[sl * 16 + k] * sp[k * 128];
        part[sl][j8] = s;
    }
    __syncthreads();
    if (tid < 128) {
        int j = tid;
        float u = 0.0f;
#pragma unroll
        for (int q = 0; q < 8; ++q) u += part[q][j];
        g_M12[c * 128 + j] = -u;
        g_Minv[c * DIM + 128 + j] = -u;
        g_Minv[(128 + j) * DIM + c] = -u;
        g_Minv[(128 + c) * DIM + 128 + j] = g_Sinv[c * 128 + j];
    }
    grid_bar(5);

    // ---- S6: M11[c][j] = Ainv[c][j] - sum_k M12[c][k] * T[j][k]
    __syncthreads();
    if (tid < 128) srow[tid] = g_M12[c * 128 + tid];
    __syncthreads();
    {
        const float* tp = &g_T[j8 * 128 + sl * 16];
        float s = 0.0f;
#pragma unroll
        for (int k = 0; k < 16; ++k) s += srow[sl * 16 + k] * tp[k];
        part[sl][j8] = s;
    }
    __syncthreads();
    if (tid < 128) {
        float s = g_Ainv[c * 128 + tid];
#pragma unroll
        for (int q = 0; q < 8; ++q) s -= part[q][tid];
        g_Minv[c * DIM + tid] = s;
    }
    grid_bar(6);

    // ---- S7: W split. CTA c handles atoms n0=4c..4c+3.
    // Wt[n][i] = sum_j Minv[j][i] * Dt[j][n]   (Minv symmetric)
    {
        int q = tid >> 8;           // 0..3
        int i = tid & 255;          // 0..255
        sdcol[q][i] = g_Dt[i * NATOMS + 4 * c + q];   // Dt[j=i][n0+q]
        __syncthreads();
        float acc = 0.0f;
#pragma unroll 8
        for (int j = 0; j < DIM; ++j) acc += g_Minv[j * DIM + i] * sdcol[q][j];
        __nv_bfloat16 h = __float2bfloat16(acc);
        __nv_bfloat16 l = __float2bfloat16(acc - __bfloat162float(h));
        g_Wt_hi[(4 * c + q) * DIM + i] = h;
        g_Wt_lo[(4 * c + q) * DIM + i] = l;
    }
}

// ---------------- split-bf16 GEMM via mma.sync.m16n8k16 ------------------------
// Grid = (4 n-blocks, 512 m-blocks): consecutive CTAs share the same A tile so
// A (Xt hi/lo, 64 MB) is read from DRAM once and served from L2 for reuse.
#define GBM 128
#define GBN 128
#define GBK 32
#define ROWB 80
#define OFF_AHI 0
#define OFF_ALO (128 * ROWB)
#define OFF_BHI (2 * 128 * ROWB)
#define OFF_BLO (3 * 128 * ROWB)
#define STAGE_B (4 * 128 * ROWB)
#define GSMEM_TOTAL (2 * STAGE_B)

__global__ __launch_bounds__(256, 2) void mma_gemm_kernel(float* __restrict__ out) {
    extern __shared__ char smem[];
    const uint32_t sb = smem_u32(smem);
    const int tid = threadIdx.x;
    const int m0 = blockIdx.y * GBM;    // m slow
    const int n0 = blockIdx.x * GBN;    // n fast -> A-tile reuse across adjacent CTAs

    const int lane = tid & 31, warp = tid >> 5;
    const int gid = lane >> 2, tig = lane & 3;
    const int wm = (warp >> 2) * 64;
    const int wn = (warp & 3) * 32;

    float acc[4][4][4];
#pragma unroll
    for (int i = 0; i < 4; ++i)
#pragma unroll
        for (int j = 0; j < 4; ++j)
#pragma unroll
            for (int q = 0; q < 4; ++q) acc[i][j][q] = 0.0f;

    const int lrow = tid >> 1;
    const int lc0 = (tid & 1) * 2;
    const __nv_bfloat16* gAh = g_Xt_hi + (size_t)(m0 + lrow) * DIM + lc0 * 8;
    const __nv_bfloat16* gAl = g_Xt_lo + (size_t)(m0 + lrow) * DIM + lc0 * 8;
    const __nv_bfloat16* gBh = g_Wt_hi + (size_t)(n0 + lrow) * DIM + lc0 * 8;
    const __nv_bfloat16* gBl = g_Wt_lo + (size_t)(n0 + lrow) * DIM + lc0 * 8;
    const uint32_t sRow = (uint32_t)(lrow * ROWB + lc0 * 16);

#define LOAD_STAGE(s, kc)                                                        \
    do {                                                                         \
        uint32_t _st = sb + (s) * STAGE_B + sRow;                                \
        int _ke = (kc) * GBK;                                                    \
        cp_async16(_st + OFF_AHI,      gAh + _ke);                               \
        cp_async16(_st + OFF_AHI + 16, gAh + _ke + 8);                           \
        cp_async16(_st + OFF_ALO,      gAl + _ke);                               \
        cp_async16(_st + OFF_ALO + 16, gAl + _ke + 8);                           \
        cp_async16(_st + OFF_BHI,      gBh + _ke);                               \
        cp_async16(_st + OFF_BHI + 16, gBh + _ke + 8);                           \
        cp_async16(_st + OFF_BLO,      gBl + _ke);                               \
        cp_async16(_st + OFF_BLO + 16, gBl + _ke + 8);                           \
    } while (0)

    LOAD_STAGE(0, 0);
    cp_commit();

    for (int kc = 0; kc < 8; ++kc) {
        const int s = kc & 1;
        if (kc < 7) {
            LOAD_STAGE(s ^ 1, kc + 1);
            cp_commit();
            cp_wait1();
        } else {
            cp_wait0();
        }
        __syncthreads();

        const uint32_t stb = sb + s * STAGE_B;
#pragma unroll
        for (int ks = 0; ks < 2; ++ks) {
            const uint32_t cb = (uint32_t)((ks * 8 + tig) * 4);
            uint32_t bh[4][2], bl[4][2];
#pragma unroll
            for (int tn = 0; tn < 4; ++tn) {
                uint32_t ro = stb + (uint32_t)((wn + tn * 8 + gid) * ROWB) + cb;
                bh[tn][0] = lds32(ro + OFF_BHI);
                bh[tn][1] = lds32(ro + OFF_BHI + 16);
                bl[tn][0] = lds32(ro + OFF_BLO);
                bl[tn][1] = lds32(ro + OFF_BLO + 16);
            }
#pragma unroll
            for (int tm = 0; tm < 4; ++tm) {
                uint32_t ro = stb + (uint32_t)((wm + tm * 16 + gid) * ROWB) + cb;
                uint32_t ah0 = lds32(ro + OFF_AHI);
                uint32_t ah1 = lds32(ro + OFF_AHI + 8 * ROWB);
                uint32_t ah2 = lds32(ro + OFF_AHI + 16);
                uint32_t ah3 = lds32(ro + OFF_AHI + 8 * ROWB + 16);
                uint32_t al0 = lds32(ro + OFF_ALO);
                uint32_t al1 = lds32(ro + OFF_ALO + 8 * ROWB);
                uint32_t al2 = lds32(ro + OFF_ALO + 16);
                uint32_t al3 = lds32(ro + OFF_ALO + 8 * ROWB + 16);
                // interleave split-MMAs: same-acc distance = 4 (breaks RAW chains)
#pragma unroll
                for (int tn = 0; tn < 4; ++tn)
                    mma16816(acc[tm][tn], ah0, ah1, ah2, ah3, bh[tn][0], bh[tn][1]);
#pragma unroll
                for (int tn = 0; tn < 4; ++tn)
                    mma16816(acc[tm][tn], ah0, ah1, ah2, ah3, bl[tn][0], bl[tn][1]);
#pragma unroll
                for (int tn = 0; tn < 4; ++tn)
                    mma16816(acc[tm][tn], al0, al1, al2, al3, bh[tn][0], bh[tn][1]);
            }
        }
        __syncthreads();
    }

#pragma unroll
    for (int tm = 0; tm < 4; ++tm) {
        int m = m0 + wm + tm * 16 + gid;
#pragma unroll
        for (int tn = 0; tn < 4; ++tn) {
            int n = n0 + wn + tn * 8 + tig * 2;
            float2 v0 = make_float2(acc[tm][tn][0], acc[tm][tn][1]);
            float2 v1 = make_float2(acc[tm][tn][2], acc[tm][tn][3]);
            *reinterpret_cast<float2*>(&out[(size_t)m * NATOMS + n]) = v0;
            *reinterpret_cast<float2*>(&out[(size_t)(m + 8) * NATOMS + n]) = v1;
        }
    }
}

// ---------------- launch --------------------------------------------------------
extern "C" void kernel_launch(void* const* d_in, const int* in_sizes, int n_in,
                              void* d_out, int out_size) {
    const float* z_e  = (const float*)d_in[0];
    const float* dict = (const float*)d_in[1];
    if (in_sizes[0] == NATOMS * DIM && in_sizes[1] == DIM * NCOLS) {
        dict = (const float*)d_in[0];
        z_e  = (const float*)d_in[1];
    }
    float* out = (float*)d_out;

    static bool attr_set = false;
    if (!attr_set) {
        cudaFuncSetAttribute(mma_gemm_kernel, cudaFuncAttributeMaxDynamicSharedMemorySize,
                             GSMEM_TOTAL);
        attr_set = true;
    }

    xt_convert_kernel<<<dim3(NCOLS / 32, DIM / 32), dim3(32, 8)>>>(z_e);   // idx 0
    prep_kernel<<<128, dim3(32, 8)>>>(dict);                               // idx 1
    persist_kernel<<<NBLK, 1024>>>(dict);                                  // idx 2
    mma_gemm_kernel<<<dim3(NATOMS / GBN, NCOLS / GBM), 256, GSMEM_TOTAL>>>(out);  // idx 3
}

// round 11
// speedup vs baseline: 1.0140x; 1.0140x over previous
#include <cuda_runtime.h>
#include <cuda_bf16.h>
#include <cstdint>

// Problem constants
#define DIM 256
#define NATOMS 512
#define NCOLS 65536

// ---------------- device scratch (no allocation allowed) ----------------
__device__ float g_G[DIM * DIM];        // Gram matrix G = D D^T  (256x256)
__device__ float g_Ainv[128 * 128];
__device__ float g_T[128 * 128];        // T = Ainv * B
__device__ float g_S[128 * 128];        // Schur complement
__device__ float g_Sinv[128 * 128];
__device__ float g_M12[128 * 128];
__device__ float g_Minv[DIM * DIM];     // G^{-1} (256x256)
__device__ float g_Dt[DIM * NATOMS];    // D (= dictionary^T), [256][512]
__device__ int   g_bar[8];              // software grid-barrier counters

// bf16 split operands (16-byte aligned for cp.async 16B)
__device__ __align__(16) __nv_bfloat16 g_Xt_hi[(size_t)NCOLS * DIM];  // [m][k]
__device__ __align__(16) __nv_bfloat16 g_Xt_lo[(size_t)NCOLS * DIM];
__device__ __align__(16) __nv_bfloat16 g_Wt_hi[NATOMS * DIM];         // [n][k]
__device__ __align__(16) __nv_bfloat16 g_Wt_lo[NATOMS * DIM];

// ================= helpers (family-portable PTX only) =================
__device__ __forceinline__ uint32_t smem_u32(const void* p) {
    uint32_t a;
    asm("{ .reg .u64 t; cvta.to.shared.u64 t, %1; cvt.u32.u64 %0, t; }" : "=r"(a) : "l"(p));
    return a;
}
__device__ __forceinline__ void cp_async16(uint32_t smem_addr, const void* gptr) {
    asm volatile("cp.async.cg.shared.global [%0], [%1], 16;" :: "r"(smem_addr), "l"(gptr));
}
__device__ __forceinline__ void cp_commit() {
    asm volatile("cp.async.commit_group;" ::: "memory");
}
__device__ __forceinline__ void cp_wait1() {
    asm volatile("cp.async.wait_group 1;" ::: "memory");
}
__device__ __forceinline__ void cp_wait0() {
    asm volatile("cp.async.wait_group 0;" ::: "memory");
}
__device__ __forceinline__ void ldsm_x4(uint32_t& r0, uint32_t& r1, uint32_t& r2, uint32_t& r3,
                                        uint32_t addr) {
    asm volatile("ldmatrix.sync.aligned.m8n8.x4.shared.b16 {%0,%1,%2,%3}, [%4];"
        : "=r"(r0), "=r"(r1), "=r"(r2), "=r"(r3) : "r"(addr));
}
__device__ __forceinline__ void ldsm_x2(uint32_t& r0, uint32_t& r1, uint32_t addr) {
    asm volatile("ldmatrix.sync.aligned.m8n8.x2.shared.b16 {%0,%1}, [%2];"
        : "=r"(r0), "=r"(r1) : "r"(addr));
}
__device__ __forceinline__ void mma16816(float* d, uint32_t a0, uint32_t a1, uint32_t a2,
                                         uint32_t a3, uint32_t b0, uint32_t b1) {
    asm volatile(
        "mma.sync.aligned.m16n8k16.row.col.f32.bf16.bf16.f32 "
        "{%0,%1,%2,%3}, {%4,%5,%6,%7}, {%8,%9}, {%0,%1,%2,%3};"
        : "+f"(d[0]), "+f"(d[1]), "+f"(d[2]), "+f"(d[3])
        : "r"(a0), "r"(a1), "r"(a2), "r"(a3), "r"(b0), "r"(b1));
}

// ---------------- prep: transpose dictionary -> g_Dt + reset barriers ----------
__global__ void prep_kernel(const float* __restrict__ dict) {
    if (blockIdx.x == 0 && threadIdx.x == 0 && threadIdx.y == 0) {
#pragma unroll
        for (int s = 0; s < 8; ++s) g_bar[s] = 0;
    }
    __shared__ float t[32][33];
    int bx = blockIdx.x & 7;     // 8 tiles along i (DIM)
    int by = blockIdx.x >> 3;    // 16 tiles along k (NATOMS)
    int x = bx * 32 + threadIdx.x;
#pragma unroll
    for (int r = 0; r < 32; r += 8) {
        int k = by * 32 + threadIdx.y + r;
        t[threadIdx.y + r][threadIdx.x] = dict[k * DIM + x];
    }
    __syncthreads();
#pragma unroll
    for (int r = 0; r < 32; r += 8) {
        int i = bx * 32 + threadIdx.y + r;
        g_Dt[i * NATOMS + by * 32 + threadIdx.x] = t[threadIdx.x][threadIdx.y + r];
    }
}

// ---------------- X [k][m] fp32 -> Xt_hi/lo [m][k] bf16 split ------------------
__global__ void xt_convert_kernel(const float* __restrict__ X) {
    __shared__ float t[32][33];
    int m0 = blockIdx.x * 32;
    int k0 = blockIdx.y * 32;
#pragma unroll
    for (int r = 0; r < 32; r += 8) {
        t[threadIdx.y + r][threadIdx.x] =
            X[(size_t)(k0 + threadIdx.y + r) * NCOLS + m0 + threadIdx.x];
    }
    __syncthreads();
#pragma unroll
    for (int r = 0; r < 32; r += 8) {
        int m = m0 + threadIdx.y + r;
        float v = t[threadIdx.x][threadIdx.y + r];
        __nv_bfloat16 h = __float2bfloat16(v);
        __nv_bfloat16 l = __float2bfloat16(v - __bfloat162float(h));
        size_t off = (size_t)m * DIM + k0 + threadIdx.x;
        g_Xt_hi[off] = h;
        g_Xt_lo[off] = l;
    }
}

// ---------------- persistent chain kernel --------------------------------------
// 128 CTAs x 1024 threads, all resident (128 <= 148 SMs). Software grid barriers.
#define NBLK 128

__device__ __forceinline__ void grid_bar(int s) {
    __syncthreads();
    if (threadIdx.x == 0) {
        __threadfence();
        atomicAdd(&g_bar[s], 1);
        while (atomicAdd(&g_bar[s], 0) < NBLK) __nanosleep(64);
        __threadfence();
    }
    __syncthreads();
}

// 1024-thread register-resident Gauss-Jordan 128x128 inverse (verified R3 code).
__device__ void gj128(int which) {
    const float* src = (which == 0) ? g_G : g_S;
    float* dst       = (which == 0) ? g_Ainv : g_Sinv;
    int lds          = (which == 0) ? DIM : 128;

    __shared__ float sh_col[128];
    __shared__ float sh_row[128];
    int tid = threadIdx.x;
    int row = tid >> 3;
    int seg = (tid & 7) << 4;
    float a[16];
#pragma unroll
    for (int c = 0; c < 16; ++c) a[c] = src[row * lds + seg + c];

    for (int k = 0; k < 128; ++k) {
#pragma unroll
        for (int c = 0; c < 16; ++c)
            if (seg + c == k) sh_col[row] = a[c];
        __syncthreads();
        float p = 1.0f / sh_col[k];
        float f = sh_col[row];
        if (row == k) {
#pragma unroll
            for (int c = 0; c < 16; ++c) {
                int j = seg + c;
                float v = (j == k) ? p : a[c] * p;
                a[c] = v;
                sh_row[j] = v;
            }
        }
        __syncthreads();
        if (row != k) {
#pragma unroll
            for (int c = 0; c < 16; ++c) {
                int j = seg + c;
                a[c] = (j == k) ? (-f * p) : (a[c] - f * sh_row[j]);
            }
        }
        __syncthreads();
    }
#pragma unroll
    for (int c = 0; c < 16; ++c) dst[row * 128 + seg + c] = a[c];
}

__global__ __launch_bounds__(1024, 1) void persist_kernel(const float* __restrict__ dict) {
    const int tid = threadIdx.x;
    const int c = blockIdx.x;           // 0..127
    __shared__ float srow[128];
    __shared__ float part[8][128];      // split-k partials
    __shared__ float sdcol[4][256];

    const int j8 = tid & 127;           // output column for split-k stages
    const int sl = tid >> 7;            // k-slice 0..7

    // ---- S0: gram. CTA c computes G rows {2c, 2c+1}; 1024 threads.
    {
        int j = tid & 255;
        int qs = tid >> 8;              // 0..3
        const float* dj = dict + j;
        const float* d0 = dict + 2 * c;
        const float* d1 = dict + 2 * c + 1;
        float s0 = 0.0f, s1 = 0.0f;
#pragma unroll 8
        for (int a = qs * 128; a < qs * 128 + 128; ++a) {
            float v = dj[a * DIM];
            s0 += d0[a * DIM] * v;
            s1 += d1[a * DIM] * v;
        }
        ((float*)part)[qs * 256 + j] = s0;
        __syncthreads();
        float t0 = 0.0f;
        if (tid < 256) {
#pragma unroll
            for (int q = 0; q < 4; ++q) t0 += ((float*)part)[q * 256 + tid];
        }
        __syncthreads();
        ((float*)part)[qs * 256 + j] = s1;
        __syncthreads();
        if (tid < 256) {
            float t1 = 0.0f;
#pragma unroll
            for (int q = 0; q < 4; ++q) t1 += ((float*)part)[q * 256 + tid];
            g_G[(2 * c) * DIM + tid] = t0;
            g_G[(2 * c + 1) * DIM + tid] = t1;
        }
    }
    grid_bar(0);

    // ---- S1: invert A11 (CTA 0 only)
    if (c == 0) gj128(0);
    grid_bar(1);

    // ---- S2: T[c][j] = sum_k Ainv[c][k] * G[k][128+j]  (1024-thread split-k)
    if (tid < 128) srow[tid] = g_Ainv[c * 128 + tid];
    __syncthreads();
    {
        const float* gp = &g_G[(sl * 16) * DIM + 128 + j8];
        float s = 0.0f;
#pragma unroll
        for (int k = 0; k < 16; ++k) s += srow[sl * 16 + k] * gp[k * DIM];
        part[sl][j8] = s;
    }
    __syncthreads();
    if (tid < 128) {
        float s = 0.0f;
#pragma unroll
        for (int q = 0; q < 8; ++q) s += part[q][tid];
        g_T[c * 128 + tid] = s;
    }
    grid_bar(2);

    // ---- S3: S[c][j] = G[128+c][128+j] - sum_k G[k][128+c] * T[k][j]
    __syncthreads();
    if (tid < 128) srow[tid] = g_G[tid * DIM + 128 + c];
    __syncthreads();
    {
        const float* tp = &g_T[(sl * 16) * 128 + j8];
        float s = 0.0f;
#pragma unroll
        for (int k = 0; k < 16; ++k) s += srow[sl * 16 + k] * tp[k * 128];
        part[sl][j8] = s;
    }
    __syncthreads();
    if (tid < 128) {
        float s = g_G[(128 + c) * DIM + 128 + tid];
#pragma unroll
        for (int q = 0; q < 8; ++q) s -= part[q][tid];
        g_S[c * 128 + tid] = s;
    }
    grid_bar(3);

    // ---- S4: invert S (CTA 0 only)
    if (c == 0) gj128(1);
    grid_bar(4);

    // ---- S5: U = T*Sinv; M12 = -U; write M12/M21/Sinv quadrants of Minv
    __syncthreads();
    if (tid < 128) srow[tid] = g_T[c * 128 + tid];
    __syncthreads();
    {
        const float* sp = &g_Sinv[(sl * 16) * 128 + j8];
        float s = 0.0f;
#pragma unroll
        for (int k = 0; k < 16; ++k) s += srow[sl * 16 + k] * sp[k * 128];
        part[sl][j8] = s;
    }
    __syncthreads();
    if (tid < 128) {
        int j = tid;
        float u = 0.0f;
#pragma unroll
        for (int q = 0; q < 8; ++q) u += part[q][j];
        g_M12[c * 128 + j] = -u;
        g_Minv[c * DIM + 128 + j] = -u;
        g_Minv[(128 + j) * DIM + c] = -u;
        g_Minv[(128 + c) * DIM + 128 + j] = g_Sinv[c * 128 + j];
    }
    grid_bar(5);

    // ---- S6: M11[c][j] = Ainv[c][j] - sum_k M12[c][k] * T[j][k]
    __syncthreads();
    if (tid < 128) srow[tid] = g_M12[c * 128 + tid];
    __syncthreads();
    {
        const float* tp = &g_T[j8 * 128 + sl * 16];
        float s = 0.0f;
#pragma unroll
        for (int k = 0; k < 16; ++k) s += srow[sl * 16 + k] * tp[k];
        part[sl][j8] = s;
    }
    __syncthreads();
    if (tid < 128) {
        float s = g_Ainv[c * 128 + tid];
#pragma unroll
        for (int q = 0; q < 8; ++q) s -= part[q][tid];
        g_Minv[c * DIM + tid] = s;
    }
    grid_bar(6);

    // ---- S7: W split. CTA c handles atoms n0=4c..4c+3.
    {
        int q = tid >> 8;           // 0..3
        int i = tid & 255;          // 0..255
        sdcol[q][i] = g_Dt[i * NATOMS + 4 * c + q];   // Dt[j=i][n0+q]
        __syncthreads();
        float acc = 0.0f;
#pragma unroll 8
        for (int j = 0; j < DIM; ++j) acc += g_Minv[j * DIM + i] * sdcol[q][j];
        __nv_bfloat16 h = __float2bfloat16(acc);
        __nv_bfloat16 l = __float2bfloat16(acc - __bfloat162float(h));
        g_Wt_hi[(4 * c + q) * DIM + i] = h;
        g_Wt_lo[(4 * c + q) * DIM + i] = l;
    }
}

// ---------------- split-bf16 GEMM via mma.sync + ldmatrix ----------------------
// Grid = (4 n-blocks, 512 m-blocks): consecutive CTAs share the same A tile (L2).
// Fragments loaded with ldmatrix: x4 per A hi/lo fragment, x2 per B hi/lo
// fragment -> 16 LDSM + 48 MMA per k16-step (was 48 scalar LDS + 48 MMA).
// ROWB=80 keeps ldmatrix's 8-row x 16B phases conflict-free
// (row offsets mod 128B: 0,80,32,112,64,16,96,48).
#define GBM 128
#define GBN 128
#define GBK 32
#define ROWB 80
#define OFF_AHI 0
#define OFF_ALO (128 * ROWB)
#define OFF_BHI (2 * 128 * ROWB)
#define OFF_BLO (3 * 128 * ROWB)
#define STAGE_B (4 * 128 * ROWB)
#define GSMEM_TOTAL (2 * STAGE_B)

__global__ __launch_bounds__(256, 2) void mma_gemm_kernel(float* __restrict__ out) {
    extern __shared__ char smem[];
    const uint32_t sb = smem_u32(smem);
    const int tid = threadIdx.x;
    const int m0 = blockIdx.y * GBM;    // m slow
    const int n0 = blockIdx.x * GBN;    // n fast -> A-tile reuse across adjacent CTAs

    const int lane = tid & 31, warp = tid >> 5;
    const int gid = lane >> 2, tig = lane & 3;
    const int wm = (warp >> 2) * 64;
    const int wn = (warp & 3) * 32;

    float acc[4][4][4];
#pragma unroll
    for (int i = 0; i < 4; ++i)
#pragma unroll
        for (int j = 0; j < 4; ++j)
#pragma unroll
            for (int q = 0; q < 4; ++q) acc[i][j][q] = 0.0f;

    const int lrow = tid >> 1;
    const int lc0 = (tid & 1) * 2;
    const __nv_bfloat16* gAh = g_Xt_hi + (size_t)(m0 + lrow) * DIM + lc0 * 8;
    const __nv_bfloat16* gAl = g_Xt_lo + (size_t)(m0 + lrow) * DIM + lc0 * 8;
    const __nv_bfloat16* gBh = g_Wt_hi + (size_t)(n0 + lrow) * DIM + lc0 * 8;
    const __nv_bfloat16* gBl = g_Wt_lo + (size_t)(n0 + lrow) * DIM + lc0 * 8;
    const uint32_t sRow = (uint32_t)(lrow * ROWB + lc0 * 16);

    // ldmatrix per-lane base offsets (within a stage):
    // A x4: lanes 0-7 -> m rows 0-7 (k lo16B), 8-15 -> m rows 8-15,
    //       16-23 -> m rows 0-7 (+16B), 24-31 -> m rows 8-15 (+16B)
    const uint32_t aLane = (uint32_t)((wm + (lane & 15)) * ROWB + (lane >> 4) * 16);
    // B x2: lanes 0-7 -> n rows 0-7 (k lo16B), 8-15 -> n rows 0-7 (+16B)
    const uint32_t bLane = (uint32_t)((wn + (lane & 7)) * ROWB + ((lane >> 3) & 1) * 16);

#define LOAD_STAGE(s, kc)                                                        \
    do {                                                                         \
        uint32_t _st = sb + (s) * STAGE_B + sRow;                                \
        int _ke = (kc) * GBK;                                                    \
        cp_async16(_st + OFF_AHI,      gAh + _ke);                               \
        cp_async16(_st + OFF_AHI + 16, gAh + _ke + 8);                           \
        cp_async16(_st + OFF_ALO,      gAl + _ke);                               \
        cp_async16(_st + OFF_ALO + 16, gAl + _ke + 8);                           \
        cp_async16(_st + OFF_BHI,      gBh + _ke);                               \
        cp_async16(_st + OFF_BHI + 16, gBh + _ke + 8);                           \
        cp_async16(_st + OFF_BLO,      gBl + _ke);                               \
        cp_async16(_st + OFF_BLO + 16, gBl + _ke + 8);                           \
    } while (0)

    LOAD_STAGE(0, 0);
    cp_commit();

    for (int kc = 0; kc < 8; ++kc) {
        const int s = kc & 1;
        if (kc < 7) {
            LOAD_STAGE(s ^ 1, kc + 1);
            cp_commit();
            cp_wait1();
        } else {
            cp_wait0();
        }
        __syncthreads();

        const uint32_t stb = sb + s * STAGE_B;
#pragma unroll
        for (int ks = 0; ks < 2; ++ks) {
            const uint32_t kOff = (uint32_t)(ks * 32);   // k16 chunk = 32 bytes
            // B fragments for all 4 n-tiles (hi + lo): 8 x LDSM.x2
            uint32_t bh[4][2], bl[4][2];
            const uint32_t bBase = stb + bLane + kOff;
#pragma unroll
            for (int tn = 0; tn < 4; ++tn) {
                ldsm_x2(bh[tn][0], bh[tn][1], bBase + OFF_BHI + tn * 8 * ROWB);
                ldsm_x2(bl[tn][0], bl[tn][1], bBase + OFF_BLO + tn * 8 * ROWB);
            }
            const uint32_t aBase = stb + aLane + kOff;
#pragma unroll
            for (int tm = 0; tm < 4; ++tm) {
                uint32_t ah[4], al[4];
                ldsm_x4(ah[0], ah[1], ah[2], ah[3], aBase + OFF_AHI + tm * 16 * ROWB);
                ldsm_x4(al[0], al[1], al[2], al[3], aBase + OFF_ALO + tm * 16 * ROWB);
                // interleave split-MMAs: same-acc distance = 4 (breaks RAW chains)
#pragma unroll
                for (int tn = 0; tn < 4; ++tn)
                    mma16816(acc[tm][tn], ah[0], ah[1], ah[2], ah[3], bh[tn][0], bh[tn][1]);
#pragma unroll
                for (int tn = 0; tn < 4; ++tn)
                    mma16816(acc[tm][tn], ah[0], ah[1], ah[2], ah[3], bl[tn][0], bl[tn][1]);
#pragma unroll
                for (int tn = 0; tn < 4; ++tn)
                    mma16816(acc[tm][tn], al[0], al[1], al[2], al[3], bh[tn][0], bh[tn][1]);
            }
        }
        __syncthreads();
    }

#pragma unroll
    for (int tm = 0; tm < 4; ++tm) {
        int m = m0 + wm + tm * 16 + gid;
#pragma unroll
        for (int tn = 0; tn < 4; ++tn) {
            int n = n0 + wn + tn * 8 + tig * 2;
            float2 v0 = make_float2(acc[tm][tn][0], acc[tm][tn][1]);
            float2 v1 = make_float2(acc[tm][tn][2], acc[tm][tn][3]);
            *reinterpret_cast<float2*>(&out[(size_t)m * NATOMS + n]) = v0;
            *reinterpret_cast<float2*>(&out[(size_t)(m + 8) * NATOMS + n]) = v1;
        }
    }
}

// ---------------- launch --------------------------------------------------------
extern "C" void kernel_launch(void* const* d_in, const int* in_sizes, int n_in,
                              void* d_out, int out_size) {
    const float* z_e  = (const float*)d_in[0];
    const float* dict = (const float*)d_in[1];
    if (in_sizes[0] == NATOMS * DIM && in_sizes[1] == DIM * NCOLS) {
        dict = (const float*)d_in[0];
        z_e  = (const float*)d_in[1];
    }
    float* out = (float*)d_out;

    static bool attr_set = false;
    if (!attr_set) {
        cudaFuncSetAttribute(mma_gemm_kernel, cudaFuncAttributeMaxDynamicSharedMemorySize,
                             GSMEM_TOTAL);
        attr_set = true;
    }

    xt_convert_kernel<<<dim3(NCOLS / 32, DIM / 32), dim3(32, 8)>>>(z_e);   // idx 0
    prep_kernel<<<128, dim3(32, 8)>>>(dict);                               // idx 1
    persist_kernel<<<NBLK, 1024>>>(dict);                                  // idx 2
    mma_gemm_kernel<<<dim3(NATOMS / GBN, NCOLS / GBM), 256, GSMEM_TOTAL>>>(out);  // idx 3
}

// round 15
// speedup vs baseline: 1.0206x; 1.0065x over previous
#include <cuda_runtime.h>
#include <cuda_bf16.h>
#include <cstdint>

// Problem constants
#define DIM 256
#define NATOMS 512
#define NCOLS 65536

// ---------------- device scratch (no allocation allowed) ----------------
__device__ float g_G[DIM * DIM];        // Gram matrix G = D D^T  (256x256)
__device__ float g_Ainv[128 * 128];
__device__ float g_T[128 * 128];        // T = Ainv * B
__device__ float g_S[128 * 128];        // Schur complement
__device__ float g_Sinv[128 * 128];
__device__ float g_M12[128 * 128];
__device__ float g_Minv[DIM * DIM];     // G^{-1} (256x256)
__device__ float g_Dt[DIM * NATOMS];    // D (= dictionary^T), [256][512]
__device__ int   g_bar[8];              // software grid-barrier counters

// bf16 split operands (16-byte aligned for cp.async 16B)
__device__ __align__(16) __nv_bfloat16 g_Xt_hi[(size_t)NCOLS * DIM];  // [m][k]
__device__ __align__(16) __nv_bfloat16 g_Xt_lo[(size_t)NCOLS * DIM];
__device__ __align__(16) __nv_bfloat16 g_Wt_hi[NATOMS * DIM];         // [n][k]
__device__ __align__(16) __nv_bfloat16 g_Wt_lo[NATOMS * DIM];

// ================= helpers (family-portable PTX only) =================
__device__ __forceinline__ uint32_t smem_u32(const void* p) {
    uint32_t a;
    asm("{ .reg .u64 t; cvta.to.shared.u64 t, %1; cvt.u32.u64 %0, t; }" : "=r"(a) : "l"(p));
    return a;
}
__device__ __forceinline__ void cp_async16(uint32_t smem_addr, const void* gptr) {
    asm volatile("cp.async.cg.shared.global [%0], [%1], 16;" :: "r"(smem_addr), "l"(gptr));
}
__device__ __forceinline__ void cp_commit() {
    asm volatile("cp.async.commit_group;" ::: "memory");
}
__device__ __forceinline__ void cp_wait1() {
    asm volatile("cp.async.wait_group 1;" ::: "memory");
}
__device__ __forceinline__ void cp_wait0() {
    asm volatile("cp.async.wait_group 0;" ::: "memory");
}
__device__ __forceinline__ void ldsm_x4(uint32_t& r0, uint32_t& r1, uint32_t& r2, uint32_t& r3,
                                        uint32_t addr) {
    asm volatile("ldmatrix.sync.aligned.m8n8.x4.shared.b16 {%0,%1,%2,%3}, [%4];"
        : "=r"(r0), "=r"(r1), "=r"(r2), "=r"(r3) : "r"(addr));
}
__device__ __forceinline__ void ldsm_x2(uint32_t& r0, uint32_t& r1, uint32_t addr) {
    asm volatile("ldmatrix.sync.aligned.m8n8.x2.shared.b16 {%0,%1}, [%2];"
        : "=r"(r0), "=r"(r1) : "r"(addr));
}
__device__ __forceinline__ void mma16816(float* d, uint32_t a0, uint32_t a1, uint32_t a2,
                                         uint32_t a3, uint32_t b0, uint32_t b1) {
    asm volatile(
        "mma.sync.aligned.m16n8k16.row.col.f32.bf16.bf16.f32 "
        "{%0,%1,%2,%3}, {%4,%5,%6,%7}, {%8,%9}, {%0,%1,%2,%3};"
        : "+f"(d[0]), "+f"(d[1]), "+f"(d[2]), "+f"(d[3])
        : "r"(a0), "r"(a1), "r"(a2), "r"(a3), "r"(b0), "r"(b1));
}

// ---------------- idx 0: no-op shim so ncu (4th-launch capture) profiles persist
__global__ void shim_kernel() {}

// ---------------- prep: transpose dictionary -> g_Dt + reset barriers ----------
__global__ void prep_kernel(const float* __restrict__ dict) {
    if (blockIdx.x == 0 && threadIdx.x == 0 && threadIdx.y == 0) {
#pragma unroll
        for (int s = 0; s < 8; ++s) g_bar[s] = 0;
    }
    __shared__ float t[32][33];
    int bx = blockIdx.x & 7;     // 8 tiles along i (DIM)
    int by = blockIdx.x >> 3;    // 16 tiles along k (NATOMS)
    int x = bx * 32 + threadIdx.x;
#pragma unroll
    for (int r = 0; r < 32; r += 8) {
        int k = by * 32 + threadIdx.y + r;
        t[threadIdx.y + r][threadIdx.x] = dict[k * DIM + x];
    }
    __syncthreads();
#pragma unroll
    for (int r = 0; r < 32; r += 8) {
        int i = bx * 32 + threadIdx.y + r;
        g_Dt[i * NATOMS + by * 32 + threadIdx.x] = t[threadIdx.x][threadIdx.y + r];
    }
}

// ---------------- X [k][m] fp32 -> Xt_hi/lo [m][k] bf16 split ------------------
__global__ void xt_convert_kernel(const float* __restrict__ X) {
    __shared__ float t[32][33];
    int m0 = blockIdx.x * 32;
    int k0 = blockIdx.y * 32;
#pragma unroll
    for (int r = 0; r < 32; r += 8) {
        t[threadIdx.y + r][threadIdx.x] =
            X[(size_t)(k0 + threadIdx.y + r) * NCOLS + m0 + threadIdx.x];
    }
    __syncthreads();
#pragma unroll
    for (int r = 0; r < 32; r += 8) {
        int m = m0 + threadIdx.y + r;
        float v = t[threadIdx.x][threadIdx.y + r];
        __nv_bfloat16 h = __float2bfloat16(v);
        __nv_bfloat16 l = __float2bfloat16(v - __bfloat162float(h));
        size_t off = (size_t)m * DIM + k0 + threadIdx.x;
        g_Xt_hi[off] = h;
        g_Xt_lo[off] = l;
    }
}

// ---------------- persistent chain kernel --------------------------------------
// 128 CTAs x 1024 threads, all resident (128 <= 148 SMs). Software grid barriers.
#define NBLK 128

__device__ __forceinline__ void grid_bar(int s) {
    __syncthreads();
    if (threadIdx.x == 0) {
        __threadfence();
        atomicAdd(&g_bar[s], 1);
        while (atomicAdd(&g_bar[s], 0) < NBLK) __nanosleep(64);
        __threadfence();
    }
    __syncthreads();
}

// 1024-thread register-resident Gauss-Jordan 128x128 inverse (verified R3 code).
__device__ void gj128(int which) {
    const float* src = (which == 0) ? g_G : g_S;
    float* dst       = (which == 0) ? g_Ainv : g_Sinv;
    int lds          = (which == 0) ? DIM : 128;

    __shared__ float sh_col[128];
    __shared__ float sh_row[128];
    int tid = threadIdx.x;
    int row = tid >> 3;
    int seg = (tid & 7) << 4;
    float a[16];
#pragma unroll
    for (int c = 0; c < 16; ++c) a[c] = src[row * lds + seg + c];

    for (int k = 0; k < 128; ++k) {
#pragma unroll
        for (int c = 0; c < 16; ++c)
            if (seg + c == k) sh_col[row] = a[c];
        __syncthreads();
        float p = 1.0f / sh_col[k];
        float f = sh_col[row];
        if (row == k) {
#pragma unroll
            for (int c = 0; c < 16; ++c) {
                int j = seg + c;
                float v = (j == k) ? p : a[c] * p;
                a[c] = v;
                sh_row[j] = v;
            }
        }
        __syncthreads();
        if (row != k) {
#pragma unroll
            for (int c = 0; c < 16; ++c) {
                int j = seg + c;
                a[c] = (j == k) ? (-f * p) : (a[c] - f * sh_row[j]);
            }
        }
        __syncthreads();
    }
#pragma unroll
    for (int c = 0; c < 16; ++c) dst[row * 128 + seg + c] = a[c];
}

__global__ __launch_bounds__(1024, 1) void persist_kernel(const float* __restrict__ dict) {
    const int tid = threadIdx.x;
    const int c = blockIdx.x;           // 0..127
    __shared__ float srow[128];
    __shared__ float part[8][128];      // split-k partials
    __shared__ float sdcol[4][256];

    const int j8 = tid & 127;           // output column for split-k stages
    const int sl = tid >> 7;            // k-slice 0..7

    // ---- S0: gram. CTA c computes G rows {2c, 2c+1}; 1024 threads.
    {
        int j = tid & 255;
        int qs = tid >> 8;              // 0..3
        const float* dj = dict + j;
        const float* d0 = dict + 2 * c;
        const float* d1 = dict + 2 * c + 1;
        float s0 = 0.0f, s1 = 0.0f;
#pragma unroll 8
        for (int a = qs * 128; a < qs * 128 + 128; ++a) {
            float v = dj[a * DIM];
            s0 += d0[a * DIM] * v;
            s1 += d1[a * DIM] * v;
        }
        ((float*)part)[qs * 256 + j] = s0;
        __syncthreads();
        float t0 = 0.0f;
        if (tid < 256) {
#pragma unroll
            for (int q = 0; q < 4; ++q) t0 += ((float*)part)[q * 256 + tid];
        }
        __syncthreads();
        ((float*)part)[qs * 256 + j] = s1;
        __syncthreads();
        if (tid < 256) {
            float t1 = 0.0f;
#pragma unroll
            for (int q = 0; q < 4; ++q) t1 += ((float*)part)[q * 256 + tid];
            g_G[(2 * c) * DIM + tid] = t0;
            g_G[(2 * c + 1) * DIM + tid] = t1;
        }
    }
    grid_bar(0);

    // ---- S1: invert A11 (CTA 0 only)
    if (c == 0) gj128(0);
    grid_bar(1);

    // ---- S2: T[c][j] = sum_k Ainv[c][k] * G[k][128+j]  (1024-thread split-k)
    if (tid < 128) srow[tid] = g_Ainv[c * 128 + tid];
    __syncthreads();
    {
        const float* gp = &g_G[(sl * 16) * DIM + 128 + j8];
        float s = 0.0f;
#pragma unroll
        for (int k = 0; k < 16; ++k) s += srow[sl * 16 + k] * gp[k * DIM];
        part[sl][j8] = s;
    }
    __syncthreads();
    if (tid < 128) {
        float s = 0.0f;
#pragma unroll
        for (int q = 0; q < 8; ++q) s += part[q][tid];
        g_T[c * 128 + tid] = s;
    }
    grid_bar(2);

    // ---- S3: S[c][j] = G[128+c][128+j] - sum_k G[k][128+c] * T[k][j]
    __syncthreads();
    if (tid < 128) srow[tid] = g_G[tid * DIM + 128 + c];
    __syncthreads();
    {
        const float* tp = &g_T[(sl * 16) * 128 + j8];
        float s = 0.0f;
#pragma unroll
        for (int k = 0; k < 16; ++k) s += srow[sl * 16 + k] * tp[k * 128];
        part[sl][j8] = s;
    }
    __syncthreads();
    if (tid < 128) {
        float s = g_G[(128 + c) * DIM + 128 + tid];
#pragma unroll
        for (int q = 0; q < 8; ++q) s -= part[q][tid];
        g_S[c * 128 + tid] = s;
    }
    grid_bar(3);

    // ---- S4: invert S (CTA 0 only)
    if (c == 0) gj128(1);
    grid_bar(4);

    // ---- S5: U = T*Sinv; M12 = -U; write M12/M21/Sinv quadrants of Minv
    __syncthreads();
    if (tid < 128) srow[tid] = g_T[c * 128 + tid];
    __syncthreads();
    {
        const float* sp = &g_Sinv[(sl * 16) * 128 + j8];
        float s = 0.0f;
#pragma unroll
        for (int k = 0; k < 16; ++k) s += srow[sl * 16 + k] * sp[k * 128];
        part[sl][j8] = s;
    }
    __syncthreads();
    if (tid < 128) {
        int j = tid;
        float u = 0.0f;
#pragma unroll
        for (int q = 0; q < 8; ++q) u += part[q][j];
        g_M12[c * 128 + j] = -u;
        g_Minv[c * DIM + 128 + j] = -u;
        g_Minv[(128 + j) * DIM + c] = -u;
        g_Minv[(128 + c) * DIM + 128 + j] = g_Sinv[c * 128 + j];
    }
    grid_bar(5);

    // ---- S6: M11[c][j] = Ainv[c][j] - sum_k M12[c][k] * T[j][k]
    __syncthreads();
    if (tid < 128) srow[tid] = g_M12[c * 128 + tid];
    __syncthreads();
    {
        const float* tp = &g_T[j8 * 128 + sl * 16];
        float s = 0.0f;
#pragma unroll
        for (int k = 0; k < 16; ++k) s += srow[sl * 16 + k] * tp[k];
        part[sl][j8] = s;
    }
    __syncthreads();
    if (tid < 128) {
        float s = g_Ainv[c * 128 + tid];
#pragma unroll
        for (int q = 0; q < 8; ++q) s -= part[q][tid];
        g_Minv[c * DIM + tid] = s;
    }
    grid_bar(6);

    // ---- S7: W split. CTA c handles atoms n0=4c..4c+3.
    {
        int q = tid >> 8;           // 0..3
        int i = tid & 255;          // 0..255
        sdcol[q][i] = g_Dt[i * NATOMS + 4 * c + q];   // Dt[j=i][n0+q]
        __syncthreads();
        float acc = 0.0f;
#pragma unroll 8
        for (int j = 0; j < DIM; ++j) acc += g_Minv[j * DIM + i] * sdcol[q][j];
        __nv_bfloat16 h = __float2bfloat16(acc);
        __nv_bfloat16 l = __float2bfloat16(acc - __bfloat162float(h));
        g_Wt_hi[(4 * c + q) * DIM + i] = h;
        g_Wt_lo[(4 * c + q) * DIM + i] = l;
    }
}

// ---------------- split-bf16 GEMM via mma.sync + ldmatrix ----------------------
// CTA tile 128m x 64n, BK=32, 8 warps (4m x 2n), warp tile 32x32.
// acc = 32 regs/thread -> __launch_bounds__(256,3) -> 3 CTAs/SM = 6 warps/SMSP
// (was 4) for latency hiding. smem 60 KB (2 stages), 3x60=180 KB/SM fits.
// Grid (8 n, 512 m): n fast -> A-tile L2 reuse; B (512 KB) L2-resident.
#define GBM 128
#define GBN 64
#define GBK 32
#define ROWB 80
#define OFF_AHI 0
#define OFF_ALO (128 * ROWB)                 // 10240
#define OFF_BHI (2 * 128 * ROWB)             // 20480
#define OFF_BLO (2 * 128 * ROWB + 64 * ROWB) // 25600
#define STAGE_B (2 * 128 * ROWB + 2 * 64 * ROWB)  // 30720
#define GSMEM_TOTAL (2 * STAGE_B)            // 61440

__global__ __launch_bounds__(256, 3) void mma_gemm_kernel(float* __restrict__ out) {
    extern __shared__ char smem[];
    const uint32_t sb = smem_u32(smem);
    const int tid = threadIdx.x;
    const int m0 = blockIdx.y * GBM;    // m slow
    const int n0 = blockIdx.x * GBN;    // n fast -> A-tile reuse across adjacent CTAs

    const int lane = tid & 31, warp = tid >> 5;
    const int gid = lane >> 2, tig = lane & 3;
    const int wm = (warp & 3) * 32;     // 4 m-warps
    const int wn = (warp >> 2) * 32;    // 2 n-warps

    float acc[2][4][4];
#pragma unroll
    for (int i = 0; i < 2; ++i)
#pragma unroll
        for (int j = 0; j < 4; ++j)
#pragma unroll
            for (int q = 0; q < 4; ++q) acc[i][j][q] = 0.0f;

    // A loads: 128 rows x 4 chunks(16B); 256 threads -> 2 chunks each
    const int lrowA = tid >> 1;
    const int lcA = (tid & 1) * 2;
    const __nv_bfloat16* gAh = g_Xt_hi + (size_t)(m0 + lrowA) * DIM + lcA * 8;
    const __nv_bfloat16* gAl = g_Xt_lo + (size_t)(m0 + lrowA) * DIM + lcA * 8;
    const uint32_t sRowA = (uint32_t)(lrowA * ROWB + lcA * 16);
    // B loads: 64 rows x 4 chunks; 256 threads -> 1 chunk each
    const int lrowB = tid >> 2;
    const int lcB = tid & 3;
    const __nv_bfloat16* gBh = g_Wt_hi + (size_t)(n0 + lrowB) * DIM + lcB * 8;
    const __nv_bfloat16* gBl = g_Wt_lo + (size_t)(n0 + lrowB) * DIM + lcB * 8;
    const uint32_t sRowB = (uint32_t)(lrowB * ROWB + lcB * 16);

    // ldmatrix per-lane base offsets
    const uint32_t aLane = (uint32_t)((wm + (lane & 15)) * ROWB + (lane >> 4) * 16);
    const uint32_t bLane = (uint32_t)((wn + (lane & 7)) * ROWB + ((lane >> 3) & 1) * 16);

#define LOAD_STAGE(s, kc)                                                        \
    do {                                                                         \
        uint32_t _st = sb + (s) * STAGE_B;                                       \
        int _ke = (kc) * GBK;                                                    \
        cp_async16(_st + OFF_AHI + sRowA,      gAh + _ke);                       \
        cp_async16(_st + OFF_AHI + sRowA + 16, gAh + _ke + 8);                   \
        cp_async16(_st + OFF_ALO + sRowA,      gAl + _ke);                       \
        cp_async16(_st + OFF_ALO + sRowA + 16, gAl + _ke + 8);                   \
        cp_async16(_st + OFF_BHI + sRowB,      gBh + _ke);                       \
        cp_async16(_st + OFF_BLO + sRowB,      gBl + _ke);                       \
    } while (0)

    LOAD_STAGE(0, 0);
    cp_commit();

    for (int kc = 0; kc < 8; ++kc) {
        const int s = kc & 1;
        if (kc < 7) {
            LOAD_STAGE(s ^ 1, kc + 1);
            cp_commit();
            cp_wait1();
        } else {
            cp_wait0();
        }
        __syncthreads();

        const uint32_t stb = sb + s * STAGE_B;
#pragma unroll
        for (int ks = 0; ks < 2; ++ks) {
            const uint32_t kOff = (uint32_t)(ks * 32);   // k16 chunk = 32 bytes
            // B fragments for all 4 n-tiles (hi + lo): 8 x LDSM.x2
            uint32_t bh[4][2], bl[4][2];
            const uint32_t bBase = stb + bLane + kOff;
#pragma unroll
            for (int tn = 0; tn < 4; ++tn) {
                ldsm_x2(bh[tn][0], bh[tn][1], bBase + OFF_BHI + tn * 8 * ROWB);
                ldsm_x2(bl[tn][0], bl[tn][1], bBase + OFF_BLO + tn * 8 * ROWB);
            }
            const uint32_t aBase = stb + aLane + kOff;
#pragma unroll
            for (int tm = 0; tm < 2; ++tm) {
                uint32_t ah[4], al[4];
                ldsm_x4(ah[0], ah[1], ah[2], ah[3], aBase + OFF_AHI + tm * 16 * ROWB);
                ldsm_x4(al[0], al[1], al[2], al[3], aBase + OFF_ALO + tm * 16 * ROWB);
                // interleave split-MMAs: same-acc distance = 4 (breaks RAW chains)
#pragma unroll
                for (int tn = 0; tn < 4; ++tn)
                    mma16816(acc[tm][tn], ah[0], ah[1], ah[2], ah[3], bh[tn][0], bh[tn][1]);
#pragma unroll
                for (int tn = 0; tn < 4; ++tn)
                    mma16816(acc[tm][tn], ah[0], ah[1], ah[2], ah[3], bl[tn][0], bl[tn][1]);
#pragma unroll
                for (int tn = 0; tn < 4; ++tn)
                    mma16816(acc[tm][tn], al[0], al[1], al[2], al[3], bh[tn][0], bh[tn][1]);
            }
        }
        __syncthreads();
    }

#pragma unroll
    for (int tm = 0; tm < 2; ++tm) {
        int m = m0 + wm + tm * 16 + gid;
#pragma unroll
        for (int tn = 0; tn < 4; ++tn) {
            int n = n0 + wn + tn * 8 + tig * 2;
            float2 v0 = make_float2(acc[tm][tn][0], acc[tm][tn][1]);
            float2 v1 = make_float2(acc[tm][tn][2], acc[tm][tn][3]);
            *reinterpret_cast<float2*>(&out[(size_t)m * NATOMS + n]) = v0;
            *reinterpret_cast<float2*>(&out[(size_t)(m + 8) * NATOMS + n]) = v1;
        }
    }
}

// ---------------- launch --------------------------------------------------------
extern "C" void kernel_launch(void* const* d_in, const int* in_sizes, int n_in,
                              void* d_out, int out_size) {
    const float* z_e  = (const float*)d_in[0];
    const float* dict = (const float*)d_in[1];
    if (in_sizes[0] == NATOMS * DIM && in_sizes[1] == DIM * NCOLS) {
        dict = (const float*)d_in[0];
        z_e  = (const float*)d_in[1];
    }
    float* out = (float*)d_out;

    static bool attr_set = false;
    if (!attr_set) {
        cudaFuncSetAttribute(mma_gemm_kernel, cudaFuncAttributeMaxDynamicSharedMemorySize,
                             GSMEM_TOTAL);
        attr_set = true;
    }

    shim_kernel<<<1, 32>>>();                                              // idx 0 (shifts capture)
    xt_convert_kernel<<<dim3(NCOLS / 32, DIM / 32), dim3(32, 8)>>>(z_e);   // idx 1
    prep_kernel<<<128, dim3(32, 8)>>>(dict);                               // idx 2
    persist_kernel<<<NBLK, 1024>>>(dict);                                  // idx 3 <- profiled
    mma_gemm_kernel<<<dim3(NATOMS / GBN, NCOLS / GBM), 256, GSMEM_TOTAL>>>(out);  // idx 4
}

// round 16
// speedup vs baseline: 2.0637x; 2.0220x over previous
#include <cuda_runtime.h>
#include <cuda_bf16.h>
#include <cstdint>

// Problem constants
#define DIM 256
#define NATOMS 512
#define NCOLS 65536
#define NBLK 128
#define NSITER 12

// ---------------- device scratch (no allocation allowed) ----------------
__device__ float g_G[DIM * DIM];        // Gram matrix G = D D^T  (256x256)
__device__ float g_Minv[DIM * DIM];     // Newton-Schulz X (even buffers / final)
__device__ float g_Xb[DIM * DIM];       // Newton-Schulz X (odd buffers)
__device__ float g_Y[DIM * DIM];        // Y = G*X
__device__ float g_Dt[DIM * NATOMS];    // D (= dictionary^T), [256][512]
__device__ int   g_bar[32];             // software grid-barrier counters
__device__ int   g_Rbits;               // Gershgorin bound (float bits, atomicMax)

// bf16 split operands (16-byte aligned for cp.async 16B)
__device__ __align__(16) __nv_bfloat16 g_Xt_hi[(size_t)NCOLS * DIM];  // [m][k]
__device__ __align__(16) __nv_bfloat16 g_Xt_lo[(size_t)NCOLS * DIM];
__device__ __align__(16) __nv_bfloat16 g_Wt_hi[NATOMS * DIM];         // [n][k]
__device__ __align__(16) __nv_bfloat16 g_Wt_lo[NATOMS * DIM];

// ================= helpers (family-portable PTX only) =================
__device__ __forceinline__ uint32_t smem_u32(const void* p) {
    uint32_t a;
    asm("{ .reg .u64 t; cvta.to.shared.u64 t, %1; cvt.u32.u64 %0, t; }" : "=r"(a) : "l"(p));
    return a;
}
__device__ __forceinline__ void cp_async16(uint32_t smem_addr, const void* gptr) {
    asm volatile("cp.async.cg.shared.global [%0], [%1], 16;" :: "r"(smem_addr), "l"(gptr));
}
__device__ __forceinline__ void cp_commit() {
    asm volatile("cp.async.commit_group;" ::: "memory");
}
__device__ __forceinline__ void cp_wait1() {
    asm volatile("cp.async.wait_group 1;" ::: "memory");
}
__device__ __forceinline__ void cp_wait0() {
    asm volatile("cp.async.wait_group 0;" ::: "memory");
}
__device__ __forceinline__ void ldsm_x4(uint32_t& r0, uint32_t& r1, uint32_t& r2, uint32_t& r3,
                                        uint32_t addr) {
    asm volatile("ldmatrix.sync.aligned.m8n8.x4.shared.b16 {%0,%1,%2,%3}, [%4];"
        : "=r"(r0), "=r"(r1), "=r"(r2), "=r"(r3) : "r"(addr));
}
__device__ __forceinline__ void ldsm_x2(uint32_t& r0, uint32_t& r1, uint32_t addr) {
    asm volatile("ldmatrix.sync.aligned.m8n8.x2.shared.b16 {%0,%1}, [%2];"
        : "=r"(r0), "=r"(r1) : "r"(addr));
}
__device__ __forceinline__ void mma16816(float* d, uint32_t a0, uint32_t a1, uint32_t a2,
                                         uint32_t a3, uint32_t b0, uint32_t b1) {
    asm volatile(
        "mma.sync.aligned.m16n8k16.row.col.f32.bf16.bf16.f32 "
        "{%0,%1,%2,%3}, {%4,%5,%6,%7}, {%8,%9}, {%0,%1,%2,%3};"
        : "+f"(d[0]), "+f"(d[1]), "+f"(d[2]), "+f"(d[3])
        : "r"(a0), "r"(a1), "r"(a2), "r"(a3), "r"(b0), "r"(b1));
}

// ---------------- prep: transpose dictionary -> g_Dt + reset barriers ----------
__global__ void prep_kernel(const float* __restrict__ dict) {
    if (blockIdx.x == 0 && threadIdx.x == 0 && threadIdx.y == 0) {
#pragma unroll
        for (int s = 0; s < 32; ++s) g_bar[s] = 0;
        g_Rbits = 0;
    }
    __shared__ float t[32][33];
    int bx = blockIdx.x & 7;     // 8 tiles along i (DIM)
    int by = blockIdx.x >> 3;    // 16 tiles along k (NATOMS)
    int x = bx * 32 + threadIdx.x;
#pragma unroll
    for (int r = 0; r < 32; r += 8) {
        int k = by * 32 + threadIdx.y + r;
        t[threadIdx.y + r][threadIdx.x] = dict[k * DIM + x];
    }
    __syncthreads();
#pragma unroll
    for (int r = 0; r < 32; r += 8) {
        int i = bx * 32 + threadIdx.y + r;
        g_Dt[i * NATOMS + by * 32 + threadIdx.x] = t[threadIdx.x][threadIdx.y + r];
    }
}

// ---------------- X [k][m] fp32 -> Xt_hi/lo [m][k] bf16 split ------------------
__global__ void xt_convert_kernel(const float* __restrict__ X) {
    __shared__ float t[32][33];
    int m0 = blockIdx.x * 32;
    int k0 = blockIdx.y * 32;
#pragma unroll
    for (int r = 0; r < 32; r += 8) {
        t[threadIdx.y + r][threadIdx.x] =
            X[(size_t)(k0 + threadIdx.y + r) * NCOLS + m0 + threadIdx.x];
    }
    __syncthreads();
#pragma unroll
    for (int r = 0; r < 32; r += 8) {
        int m = m0 + threadIdx.y + r;
        float v = t[threadIdx.x][threadIdx.y + r];
        __nv_bfloat16 h = __float2bfloat16(v);
        __nv_bfloat16 l = __float2bfloat16(v - __bfloat162float(h));
        size_t off = (size_t)m * DIM + k0 + threadIdx.x;
        g_Xt_hi[off] = h;
        g_Xt_lo[off] = l;
    }
}

// ---------------- persistent chain: gram -> Newton-Schulz inverse -> W ---------
// 128 CTAs x 1024 threads, all resident. Software grid barriers.

__device__ __forceinline__ void grid_bar(int s) {
    __syncthreads();
    if (threadIdx.x == 0) {
        __threadfence();
        atomicAdd(&g_bar[s], 1);
        while (atomicAdd(&g_bar[s], 0) < NBLK) __nanosleep(64);
        __threadfence();
    }
    __syncthreads();
}

// Tile matmul for 256x256 matrices: CTA c computes rows [(c>>4)*32, +32),
// cols [(c&15)*16, +16). 2x2 register blocking, 8-way split-k, smem-staged.
// mode 0: C = A*B.  mode 1: C = 2*X2 - A*B  (Newton-Schulz update).
// sh layout: sA [32][260] (8320 f), sB [256][16] (4096 f); partials reuse sh.
__device__ void ns_matmul(float* sh, const float* A, const float* B, float* C,
                          const float* X2, int mode) {
    float* sA = sh;
    float* sB = sh + 32 * 260;
    const int tid = threadIdx.x;
    const int c = blockIdx.x;
    const int r0 = (c >> 4) * 32;
    const int j0 = (c & 15) * 16;

    // load A rows r0..r0+31 (contiguous 32 KB) into padded sA
    {
        const float4* src = (const float4*)(A + r0 * 256);
        for (int i = tid; i < 2048; i += 1024) {
            int row = i >> 6, qc = i & 63;
            ((float4*)(sA + row * 260))[qc] = src[i];
        }
    }
    // load B cols j0..j0+15 (16 floats per row)
    {
        int k = tid >> 2, q = tid & 3;
        *((float4*)(sB + k * 16 + q * 4)) = *((const float4*)(B + k * 256 + j0 + q * 4));
    }
    __syncthreads();

    const int sl = tid >> 7;       // k-slice 0..7 (32 k each)
    const int og = tid & 127;
    const int rg = og >> 3;        // row pair 0..15
    const int cg = og & 7;         // col pair 0..7
    const float* pa0 = sA + (rg * 2 + 0) * 260 + sl * 32;
    const float* pa1 = sA + (rg * 2 + 1) * 260 + sl * 32;
    const float* pb  = sB + (sl * 32) * 16 + cg * 2;
    float a00 = 0.f, a01 = 0.f, a10 = 0.f, a11 = 0.f;
#pragma unroll
    for (int k = 0; k < 32; ++k) {
        float av0 = pa0[k], av1 = pa1[k];
        float2 bv = *((const float2*)(pb + k * 16));
        a00 += av0 * bv.x; a01 += av0 * bv.y;
        a10 += av1 * bv.x; a11 += av1 * bv.y;
    }
    __syncthreads();
    ((float4*)sh)[tid] = make_float4(a00, a01, a10, a11);
    __syncthreads();
    if (tid < 512) {
        int oo = tid >> 2;          // 0..127
        int q  = tid & 3;
        float s = 0.f;
#pragma unroll
        for (int p = 0; p < 8; ++p) s += sh[(p * 128 + oo) * 4 + q];
        int rg2 = oo >> 3, cg2 = oo & 7;
        int r  = r0 + rg2 * 2 + (q >> 1);
        int jj = j0 + cg2 * 2 + (q & 1);
        float v = s;
        if (mode) v = 2.0f * X2[r * 256 + jj] - s;
        C[r * 256 + jj] = v;
    }
    __syncthreads();
}

#define PERSIST_SMEM ((32 * 260 + 256 * 16) * 4)

__global__ __launch_bounds__(1024, 1) void persist_kernel(const float* __restrict__ dict) {
    extern __shared__ float sh[];
    const int tid = threadIdx.x;
    const int c = blockIdx.x;           // 0..127

    // ---- S0: gram. CTA c computes G rows {2c, 2c+1}; 4-way split over atoms.
    {
        int j = tid & 255;
        int qs = tid >> 8;              // 0..3
        const float* dj = dict + j;
        const float* d0 = dict + 2 * c;
        const float* d1 = dict + 2 * c + 1;
        float s0 = 0.0f, s1 = 0.0f;
#pragma unroll 8
        for (int a = qs * 128; a < qs * 128 + 128; ++a) {
            float v = dj[a * DIM];
            s0 += d0[a * DIM] * v;
            s1 += d1[a * DIM] * v;
        }
        sh[qs * 256 + j] = s0;
        __syncthreads();
        float t0 = 0.0f;
        if (tid < 256) {
#pragma unroll
            for (int q = 0; q < 4; ++q) t0 += sh[q * 256 + tid];
        }
        __syncthreads();
        sh[qs * 256 + j] = s1;
        __syncthreads();
        if (tid < 256) {
            float t1 = 0.0f;
#pragma unroll
            for (int q = 0; q < 4; ++q) t1 += sh[q * 256 + tid];
            g_G[(2 * c) * DIM + tid] = t0;
            g_G[(2 * c + 1) * DIM + tid] = t1;
        }
    }
    grid_bar(0);

    // ---- S1: Gershgorin bound R = max abs row sum (guaranteed >= lambda_max)
    {
        float v = 0.f;
        if (tid < 512) {
            int r = 2 * c + (tid >> 8), j = tid & 255;
            v = fabsf(g_G[r * 256 + j]);
#pragma unroll
            for (int o = 16; o; o >>= 1) v += __shfl_xor_sync(0xFFFFFFFFu, v, o);
        }
        __syncthreads();
        if (tid < 512 && (tid & 31) == 0) sh[tid >> 5] = v;
        __syncthreads();
        if (tid < 2) {
            float s = 0.f;
#pragma unroll
            for (int w = 0; w < 8; ++w) s += sh[tid * 8 + w];
            atomicMax(&g_Rbits, __float_as_int(s));
        }
        __syncthreads();
    }
    grid_bar(1);

    // ---- S2: X1 = alpha*(2I - alpha*G)  (one free NS step from X0 = alpha*I)
    {
        float alpha = 1.0f / __int_as_float(g_Rbits);
        if (tid < 512) {
            int r = 2 * c + (tid >> 8), j = tid & 255;
            float gv = g_G[r * 256 + j];
            g_Minv[r * 256 + j] = alpha * ((r == j ? 2.0f : 0.0f) - alpha * gv);
        }
    }
    grid_bar(2);

    // ---- S3: Newton-Schulz iterations: X <- 2X - X*(G*X)
    for (int it = 0; it < NSITER; ++it) {
        const float* X = (it & 1) ? g_Xb : g_Minv;
        float* Xn      = (it & 1) ? g_Minv : g_Xb;
        ns_matmul(sh, g_G, X, g_Y, nullptr, 0);    // Y = G*X
        grid_bar(3 + 2 * it);
        ns_matmul(sh, X, g_Y, Xn, X, 1);           // Xn = 2X - X*Y
        grid_bar(4 + 2 * it);
    }
    // NSITER even -> final inverse in g_Minv (symmetric).

    // ---- S4: W split. CTA c handles atoms n0=4c..4c+3.
    // Wt[n][i] = sum_j Minv[j][i] * Dt[j][n]   (Minv symmetric)
    {
        int q = tid >> 8;           // 0..3
        int i = tid & 255;          // 0..255
        sh[q * 256 + i] = g_Dt[i * NATOMS + 4 * c + q];   // Dt[j=i][n0+q]
        __syncthreads();
        float acc = 0.0f;
#pragma unroll 8
        for (int j = 0; j < DIM; ++j) acc += g_Minv[j * DIM + i] * sh[q * 256 + j];
        __nv_bfloat16 h = __float2bfloat16(acc);
        __nv_bfloat16 l = __float2bfloat16(acc - __bfloat162float(h));
        g_Wt_hi[(4 * c + q) * DIM + i] = h;
        g_Wt_lo[(4 * c + q) * DIM + i] = l;
    }
}

// ---------------- split-bf16 GEMM via mma.sync + ldmatrix ----------------------
// CTA tile 128m x 64n, BK=32, 8 warps (4m x 2n), warp tile 32x32.
// __launch_bounds__(256,3) -> 3 CTAs/SM = 6 warps/SMSP. smem 60 KB (2 stages).
// Grid (8 n, 512 m): n fast -> A-tile L2 reuse; B (512 KB) L2-resident.
#define GBM 128
#define GBN 64
#define GBK 32
#define ROWB 80
#define OFF_AHI 0
#define OFF_ALO (128 * ROWB)                 // 10240
#define OFF_BHI (2 * 128 * ROWB)             // 20480
#define OFF_BLO (2 * 128 * ROWB + 64 * ROWB) // 25600
#define STAGE_B (2 * 128 * ROWB + 2 * 64 * ROWB)  // 30720
#define GSMEM_TOTAL (2 * STAGE_B)            // 61440

__global__ __launch_bounds__(256, 3) void mma_gemm_kernel(float* __restrict__ out) {
    extern __shared__ char smem[];
    const uint32_t sb = smem_u32(smem);
    const int tid = threadIdx.x;
    const int m0 = blockIdx.y * GBM;    // m slow
    const int n0 = blockIdx.x * GBN;    // n fast -> A-tile reuse across adjacent CTAs

    const int lane = tid & 31, warp = tid >> 5;
    const int gid = lane >> 2, tig = lane & 3;
    const int wm = (warp & 3) * 32;     // 4 m-warps
    const int wn = (warp >> 2) * 32;    // 2 n-warps

    float acc[2][4][4];
#pragma unroll
    for (int i = 0; i < 2; ++i)
#pragma unroll
        for (int j = 0; j < 4; ++j)
#pragma unroll
            for (int q = 0; q < 4; ++q) acc[i][j][q] = 0.0f;

    const int lrowA = tid >> 1;
    const int lcA = (tid & 1) * 2;
    const __nv_bfloat16* gAh = g_Xt_hi + (size_t)(m0 + lrowA) * DIM + lcA * 8;
    const __nv_bfloat16* gAl = g_Xt_lo + (size_t)(m0 + lrowA) * DIM + lcA * 8;
    const uint32_t sRowA = (uint32_t)(lrowA * ROWB + lcA * 16);
    const int lrowB = tid >> 2;
    const int lcB = tid & 3;
    const __nv_bfloat16* gBh = g_Wt_hi + (size_t)(n0 + lrowB) * DIM + lcB * 8;
    const __nv_bfloat16* gBl = g_Wt_lo + (size_t)(n0 + lrowB) * DIM + lcB * 8;
    const uint32_t sRowB = (uint32_t)(lrowB * ROWB + lcB * 16);

    const uint32_t aLane = (uint32_t)((wm + (lane & 15)) * ROWB + (lane >> 4) * 16);
    const uint32_t bLane = (uint32_t)((wn + (lane & 7)) * ROWB + ((lane >> 3) & 1) * 16);

#define LOAD_STAGE(s, kc)                                                        \
    do {                                                                         \
        uint32_t _st = sb + (s) * STAGE_B;                                       \
        int _ke = (kc) * GBK;                                                    \
        cp_async16(_st + OFF_AHI + sRowA,      gAh + _ke);                       \
        cp_async16(_st + OFF_AHI + sRowA + 16, gAh + _ke + 8);                   \
        cp_async16(_st + OFF_ALO + sRowA,      gAl + _ke);                       \
        cp_async16(_st + OFF_ALO + sRowA + 16, gAl + _ke + 8);                   \
        cp_async16(_st + OFF_BHI + sRowB,      gBh + _ke);                       \
        cp_async16(_st + OFF_BLO + sRowB,      gBl + _ke);                       \
    } while (0)

    LOAD_STAGE(0, 0);
    cp_commit();

    for (int kc = 0; kc < 8; ++kc) {
        const int s = kc & 1;
        if (kc < 7) {
            LOAD_STAGE(s ^ 1, kc + 1);
            cp_commit();
            cp_wait1();
        } else {
            cp_wait0();
        }
        __syncthreads();

        const uint32_t stb = sb + s * STAGE_B;
#pragma unroll
        for (int ks = 0; ks < 2; ++ks) {
            const uint32_t kOff = (uint32_t)(ks * 32);
            uint32_t bh[4][2], bl[4][2];
            const uint32_t bBase = stb + bLane + kOff;
#pragma unroll
            for (int tn = 0; tn < 4; ++tn) {
                ldsm_x2(bh[tn][0], bh[tn][1], bBase + OFF_BHI + tn * 8 * ROWB);
                ldsm_x2(bl[tn][0], bl[tn][1], bBase + OFF_BLO + tn * 8 * ROWB);
            }
            const uint32_t aBase = stb + aLane + kOff;
#pragma unroll
            for (int tm = 0; tm < 2; ++tm) {
                uint32_t ah[4], al[4];
                ldsm_x4(ah[0], ah[1], ah[2], ah[3], aBase + OFF_AHI + tm * 16 * ROWB);
                ldsm_x4(al[0], al[1], al[2], al[3], aBase + OFF_ALO + tm * 16 * ROWB);
#pragma unroll
                for (int tn = 0; tn < 4; ++tn)
                    mma16816(acc[tm][tn], ah[0], ah[1], ah[2], ah[3], bh[tn][0], bh[tn][1]);
#pragma unroll
                for (int tn = 0; tn < 4; ++tn)
                    mma16816(acc[tm][tn], ah[0], ah[1], ah[2], ah[3], bl[tn][0], bl[tn][1]);
#pragma unroll
                for (int tn = 0; tn < 4; ++tn)
                    mma16816(acc[tm][tn], al[0], al[1], al[2], al[3], bh[tn][0], bh[tn][1]);
            }
        }
        __syncthreads();
    }

#pragma unroll
    for (int tm = 0; tm < 2; ++tm) {
        int m = m0 + wm + tm * 16 + gid;
#pragma unroll
        for (int tn = 0; tn < 4; ++tn) {
            int n = n0 + wn + tn * 8 + tig * 2;
            float2 v0 = make_float2(acc[tm][tn][0], acc[tm][tn][1]);
            float2 v1 = make_float2(acc[tm][tn][2], acc[tm][tn][3]);
            *reinterpret_cast<float2*>(&out[(size_t)m * NATOMS + n]) = v0;
            *reinterpret_cast<float2*>(&out[(size_t)(m + 8) * NATOMS + n]) = v1;
        }
    }
}

// ---------------- launch --------------------------------------------------------
extern "C" void kernel_launch(void* const* d_in, const int* in_sizes, int n_in,
                              void* d_out, int out_size) {
    const float* z_e  = (const float*)d_in[0];
    const float* dict = (const float*)d_in[1];
    if (in_sizes[0] == NATOMS * DIM && in_sizes[1] == DIM * NCOLS) {
        dict = (const float*)d_in[0];
        z_e  = (const float*)d_in[1];
    }
    float* out = (float*)d_out;

    static bool attr_set = false;
    if (!attr_set) {
        cudaFuncSetAttribute(mma_gemm_kernel, cudaFuncAttributeMaxDynamicSharedMemorySize,
                             GSMEM_TOTAL);
        cudaFuncSetAttribute(persist_kernel, cudaFuncAttributeMaxDynamicSharedMemorySize,
                             PERSIST_SMEM);
        attr_set = true;
    }

    xt_convert_kernel<<<dim3(NCOLS / 32, DIM / 32), dim3(32, 8)>>>(z_e);   // idx 0
    prep_kernel<<<128, dim3(32, 8)>>>(dict);                               // idx 1
    persist_kernel<<<NBLK, 1024, PERSIST_SMEM>>>(dict);                    // idx 2
    mma_gemm_kernel<<<dim3(NATOMS / GBN, NCOLS / GBM), 256, GSMEM_TOTAL>>>(out);  // idx 3 <- profiled
}